// round 13
// baseline (speedup 1.0000x reference)
#include <cuda_runtime.h>
#include <cuda_bf16.h>

#define D_TOTAL   8388608
#define TABLE_N   1024
#define NBLOCKS   592    /* 4 x 148 SMs — half-occupancy concurrency probe */
#define NTHREADS  256

__device__ float g_partials[NBLOCKS];
__device__ unsigned int g_counter = 0;

__global__ __launch_bounds__(NTHREADS) void phasecell_main(
    const int* __restrict__ ctx_phase,
    const int* __restrict__ ctx_mag,
    const int* __restrict__ self_phase,
    const int* __restrict__ self_mag,
    const float* __restrict__ cos_table,
    const float* __restrict__ exp_table,
    const float* __restrict__ cos_grad_table,
    const float* __restrict__ exp_grad_table,
    float* __restrict__ out)
{
    __shared__ float2 phase_tab[TABLE_N];  // (cos, dcos)
    __shared__ float2 mag_tab[TABLE_N];    // (exp, dexp)
    __shared__ float red[NTHREADS / 32];

    const int tid  = threadIdx.x;
    const int lane = tid & 31;
    for (int i = tid; i < TABLE_N; i += NTHREADS) {
        phase_tab[i] = make_float2(cos_table[i], cos_grad_table[i]);
        mag_tab[i]   = make_float2(exp_table[i], exp_grad_table[i]);
    }
    __syncthreads();

    const int4* cp4 = (const int4*)ctx_phase;
    const int4* sp4 = (const int4*)self_phase;
    const int4* cm4 = (const int4*)ctx_mag;
    const int4* sm4 = (const int4*)self_mag;

    float* __restrict__ out_phase = out;
    float* __restrict__ out_mag   = out + (size_t)D_TOTAL;
    float* __restrict__ out_sig   = out + (size_t)2 * D_TOTAL;
    // grad streams start at odd float offset (3D+1)/(4D+1); aligned-shifted
    // store scheme below. These bases are 16B-aligned.
    float* __restrict__ gp_base = out + (size_t)3 * D_TOTAL;
    float* __restrict__ gm_base = out + (size_t)4 * D_TOTAL;

    // Warp-chunked round-robin: chunk = 64 consecutive float4 vectors (1KB
    // per stream per warp). nvec = 2^21 = 64 * 32768 exactly.
    const int nchunks = (D_TOTAL / 4) / 64;                      // 32768
    const int nwarps  = gridDim.x * (NTHREADS / 32);             // 4736
    const int wglobal = (blockIdx.x * NTHREADS + tid) >> 5;

    float acc = 0.0f;

    for (int ch = wglobal; ch < nchunks; ch += nwarps) {
        const int v0 = ch * 64 + lane;
        const int v1 = v0 + 32;

        // ---- all loads grouped: 8x LDG.128, two 512B bursts per stream ----
        int4 a0 = __ldcs(&cp4[v0]); int4 a1 = __ldcs(&cp4[v1]);
        int4 b0 = __ldcs(&sp4[v0]); int4 b1 = __ldcs(&sp4[v1]);
        int4 c0 = __ldcs(&cm4[v0]); int4 c1 = __ldcs(&cm4[v1]);
        int4 d0 = __ldcs(&sm4[v0]); int4 d1 = __ldcs(&sm4[v1]);

        int p00 = (a0.x + b0.x) & (TABLE_N - 1);
        int p01 = (a0.y + b0.y) & (TABLE_N - 1);
        int p02 = (a0.z + b0.z) & (TABLE_N - 1);
        int p03 = (a0.w + b0.w) & (TABLE_N - 1);
        int m00 = (c0.x + d0.x) & (TABLE_N - 1);
        int m01 = (c0.y + d0.y) & (TABLE_N - 1);
        int m02 = (c0.z + d0.z) & (TABLE_N - 1);
        int m03 = (c0.w + d0.w) & (TABLE_N - 1);
        int p10 = (a1.x + b1.x) & (TABLE_N - 1);
        int p11 = (a1.y + b1.y) & (TABLE_N - 1);
        int p12 = (a1.z + b1.z) & (TABLE_N - 1);
        int p13 = (a1.w + b1.w) & (TABLE_N - 1);
        int m10 = (c1.x + d1.x) & (TABLE_N - 1);
        int m11 = (c1.y + d1.y) & (TABLE_N - 1);
        int m12 = (c1.z + d1.z) & (TABLE_N - 1);
        int m13 = (c1.w + d1.w) & (TABLE_N - 1);

        float2 A0 = phase_tab[p00], A1 = phase_tab[p01], A2 = phase_tab[p02], A3 = phase_tab[p03];
        float2 B0 = mag_tab[m00],   B1 = mag_tab[m01],   B2 = mag_tab[m02],   B3 = mag_tab[m03];
        float2 C0 = phase_tab[p10], C1 = phase_tab[p11], C2 = phase_tab[p12], C3 = phase_tab[p13];
        float2 E0 = mag_tab[m10],   E1 = mag_tab[m11],   E2 = mag_tab[m12],   E3 = mag_tab[m13];

        float s00 = A0.x * B0.x, s01 = A1.x * B1.x, s02 = A2.x * B2.x, s03 = A3.x * B3.x;
        float s10 = C0.x * E0.x, s11 = C1.x * E1.x, s12 = C2.x * E2.x, s13 = C3.x * E3.x;
        acc += ((s00 + s01) + (s02 + s03)) + ((s10 + s11) + (s12 + s13));

        // ---- stores grouped per stream: back-to-back 512B bursts = 1KB ----
        __stcs((float4*)out_phase + v0, make_float4((float)p00, (float)p01, (float)p02, (float)p03));
        __stcs((float4*)out_phase + v1, make_float4((float)p10, (float)p11, (float)p12, (float)p13));
        __stcs((float4*)out_mag + v0, make_float4((float)m00, (float)m01, (float)m02, (float)m03));
        __stcs((float4*)out_mag + v1, make_float4((float)m10, (float)m11, (float)m12, (float)m13));
        __stcs((float4*)out_sig + v0, make_float4(s00, s01, s02, s03));
        __stcs((float4*)out_sig + v1, make_float4(s10, s11, s12, s13));

        float gp00 = A0.y * B0.x, gp01 = A1.y * B1.x, gp02 = A2.y * B2.x, gp03 = A3.y * B3.x;
        float gm00 = A0.x * B0.y, gm01 = A1.x * B1.y, gm02 = A2.x * B2.y, gm03 = A3.x * B3.y;
        float gp10 = C0.y * E0.x, gp11 = C1.y * E1.x, gp12 = C2.y * E2.x, gp13 = C3.y * E3.x;
        float gm10 = C0.x * E0.y, gm11 = C1.x * E1.y, gm12 = C2.x * E2.y, gm13 = C3.x * E3.y;

        float q0 = __shfl_down_sync(0xFFFFFFFFu, gp00, 1);
        float q1 = __shfl_down_sync(0xFFFFFFFFu, gp01, 1);
        float q2 = __shfl_down_sync(0xFFFFFFFFu, gp02, 1);
        float r0 = __shfl_down_sync(0xFFFFFFFFu, gm00, 1);
        float r1 = __shfl_down_sync(0xFFFFFFFFu, gm01, 1);
        float r2 = __shfl_down_sync(0xFFFFFFFFu, gm02, 1);
        float u0 = __shfl_down_sync(0xFFFFFFFFu, gp10, 1);
        float u1 = __shfl_down_sync(0xFFFFFFFFu, gp11, 1);
        float u2 = __shfl_down_sync(0xFFFFFFFFu, gp12, 1);
        float w0 = __shfl_down_sync(0xFFFFFFFFu, gm10, 1);
        float w1 = __shfl_down_sync(0xFFFFFFFFu, gm11, 1);
        float w2 = __shfl_down_sync(0xFFFFFFFFu, gm12, 1);

        if (lane < 31) {
            __stcs((float4*)gp_base + v0 + 1, make_float4(gp03, q0, q1, q2));
            __stcs((float4*)gp_base + v1 + 1, make_float4(gp13, u0, u1, u2));
            __stcs((float4*)gm_base + v0 + 1, make_float4(gm03, r0, r1, r2));
            __stcs((float4*)gm_base + v1 + 1, make_float4(gm13, w0, w1, w2));
        } else {
            gp_base[4 * v0 + 4] = gp03;
            gm_base[4 * v0 + 4] = gm03;
            gp_base[4 * v1 + 4] = gp13;
            gm_base[4 * v1 + 4] = gm13;
        }
        if (lane == 0) {
            gp_base[4 * v0 + 1] = gp00;
            *(float2*)&gp_base[4 * v0 + 2] = make_float2(gp01, gp02);
            gm_base[4 * v0 + 1] = gm00;
            *(float2*)&gm_base[4 * v0 + 2] = make_float2(gm01, gm02);
            gp_base[4 * v1 + 1] = gp10;
            *(float2*)&gp_base[4 * v1 + 2] = make_float2(gp11, gp12);
            gm_base[4 * v1 + 1] = gm10;
            *(float2*)&gm_base[4 * v1 + 2] = make_float2(gm11, gm12);
        }
    }

#if __CUDA_ARCH__ >= 900
    cudaTriggerProgrammaticLaunchCompletion();
#endif

    // Deterministic block reduction
    #pragma unroll
    for (int off = 16; off > 0; off >>= 1)
        acc += __shfl_down_sync(0xFFFFFFFFu, acc, off);
    if (lane == 0) red[tid >> 5] = acc;
    __syncthreads();
    if (tid == 0) {
        float s = 0.0f;
        #pragma unroll
        for (int w = 0; w < NTHREADS / 32; w++) s += red[w];
        g_partials[blockIdx.x] = s;
        __threadfence();                       // release partial
        atomicAdd(&g_counter, 1u);             // signal completion
    }
}

__global__ __launch_bounds__(1024) void phasecell_reduce(float* __restrict__ out)
{
    __shared__ float red[32];
    const int tid = threadIdx.x;

    // Data-level handshake: wait until all primary blocks released partials.
    if (tid == 0) {
        while (atomicAdd(&g_counter, 0u) < (unsigned)NBLOCKS) {
#if __CUDA_ARCH__ >= 700
            __nanosleep(64);
#endif
        }
        __threadfence();                       // acquire
    }
    __syncthreads();

    // 592 partials = 148 float4 vectors: single load round (L2).
    float a = 0.0f;
    if (tid < NBLOCKS / 4) {
        const float* p = &g_partials[tid * 4];
        float x = __ldcg(&p[0]);
        float y = __ldcg(&p[1]);
        float z = __ldcg(&p[2]);
        float w = __ldcg(&p[3]);
        a = (x + y) + (z + w);
    }
    #pragma unroll
    for (int off = 16; off > 0; off >>= 1)
        a += __shfl_down_sync(0xFFFFFFFFu, a, off);
    if ((tid & 31) == 0) red[tid >> 5] = a;
    __syncthreads();
    if (tid == 0) {
        float s = 0.0f;
        #pragma unroll
        for (int w = 0; w < 32; w++) s += red[w];
        out[(size_t)3 * D_TOTAL] = s;  // strength scalar
        g_counter = 0;                 // reset for next graph replay
    }
}

extern "C" void kernel_launch(void* const* d_in, const int* in_sizes, int n_in,
                              void* d_out, int out_size)
{
    const int*   ctx_phase  = (const int*)d_in[0];
    const int*   ctx_mag    = (const int*)d_in[1];
    const int*   self_phase = (const int*)d_in[2];
    const int*   self_mag   = (const int*)d_in[3];
    const float* cos_t      = (const float*)d_in[4];
    const float* exp_t      = (const float*)d_in[5];
    const float* cos_g      = (const float*)d_in[6];
    const float* exp_g      = (const float*)d_in[7];
    float* out = (float*)d_out;

    phasecell_main<<<NBLOCKS, NTHREADS>>>(ctx_phase, ctx_mag, self_phase, self_mag,
                                          cos_t, exp_t, cos_g, exp_g, out);

    cudaLaunchConfig_t cfg = {};
    cfg.gridDim  = dim3(1, 1, 1);
    cfg.blockDim = dim3(1024, 1, 1);
    cfg.dynamicSmemBytes = 0;
    cfg.stream = 0;

    cudaLaunchAttribute attrs[1];
    attrs[0].id = cudaLaunchAttributeProgrammaticStreamSerialization;
    attrs[0].val.programmaticStreamSerializationAllowed = 1;
    cfg.attrs = attrs;
    cfg.numAttrs = 1;

    cudaError_t e = cudaLaunchKernelEx(&cfg, phasecell_reduce, out);
    if (e != cudaSuccess) {
        phasecell_reduce<<<1, 1024>>>(out);
    }
}

// round 14
// speedup vs baseline: 1.0287x; 1.0287x over previous
#include <cuda_runtime.h>
#include <cuda_bf16.h>

#define D_TOTAL   8388608
#define TABLE_N   1024
#define NBLOCKS   1184   /* 8 x 148 effective SMs — max occupancy, empirically best */
#define NTHREADS  256

__device__ float g_partials[NBLOCKS];
__device__ unsigned int g_counter = 0;

__global__ __launch_bounds__(NTHREADS) void phasecell_main(
    const int* __restrict__ ctx_phase,
    const int* __restrict__ ctx_mag,
    const int* __restrict__ self_phase,
    const int* __restrict__ self_mag,
    const float* __restrict__ cos_table,
    const float* __restrict__ exp_table,
    const float* __restrict__ cos_grad_table,
    const float* __restrict__ exp_grad_table,
    float* __restrict__ out)
{
    __shared__ float2 phase_tab[TABLE_N];  // (cos, dcos)
    __shared__ float2 mag_tab[TABLE_N];    // (exp, dexp)
    __shared__ float red[NTHREADS / 32];

    const int tid  = threadIdx.x;
    const int lane = tid & 31;
    for (int i = tid; i < TABLE_N; i += NTHREADS) {
        phase_tab[i] = make_float2(cos_table[i], cos_grad_table[i]);
        mag_tab[i]   = make_float2(exp_table[i], exp_grad_table[i]);
    }
    __syncthreads();

    const int4* cp4 = (const int4*)ctx_phase;
    const int4* sp4 = (const int4*)self_phase;
    const int4* cm4 = (const int4*)ctx_mag;
    const int4* sm4 = (const int4*)self_mag;

    float* __restrict__ out_phase = out;
    float* __restrict__ out_mag   = out + (size_t)D_TOTAL;
    float* __restrict__ out_sig   = out + (size_t)2 * D_TOTAL;
    // grad streams start at odd float offset (3D+1)/(4D+1); aligned-shifted
    // store scheme below. These bases are 16B-aligned.
    float* __restrict__ gp_base = out + (size_t)3 * D_TOTAL;
    float* __restrict__ gm_base = out + (size_t)4 * D_TOTAL;

    // Warp-chunked round-robin: chunk = 64 consecutive float4 vectors (1KB
    // per stream per warp). nvec = 2^21 = 64 * 32768 exactly.
    const int nchunks = (D_TOTAL / 4) / 64;                      // 32768
    const int nwarps  = gridDim.x * (NTHREADS / 32);             // 9472
    const int wglobal = (blockIdx.x * NTHREADS + tid) >> 5;

    float acc = 0.0f;

    for (int ch = wglobal; ch < nchunks; ch += nwarps) {
        const int v0 = ch * 64 + lane;
        const int v1 = v0 + 32;

        // ---- all loads grouped: 8x LDG.128, two 512B bursts per stream ----
        int4 a0 = __ldcs(&cp4[v0]); int4 a1 = __ldcs(&cp4[v1]);
        int4 b0 = __ldcs(&sp4[v0]); int4 b1 = __ldcs(&sp4[v1]);
        int4 c0 = __ldcs(&cm4[v0]); int4 c1 = __ldcs(&cm4[v1]);
        int4 d0 = __ldcs(&sm4[v0]); int4 d1 = __ldcs(&sm4[v1]);

        int p00 = (a0.x + b0.x) & (TABLE_N - 1);
        int p01 = (a0.y + b0.y) & (TABLE_N - 1);
        int p02 = (a0.z + b0.z) & (TABLE_N - 1);
        int p03 = (a0.w + b0.w) & (TABLE_N - 1);
        int m00 = (c0.x + d0.x) & (TABLE_N - 1);
        int m01 = (c0.y + d0.y) & (TABLE_N - 1);
        int m02 = (c0.z + d0.z) & (TABLE_N - 1);
        int m03 = (c0.w + d0.w) & (TABLE_N - 1);
        int p10 = (a1.x + b1.x) & (TABLE_N - 1);
        int p11 = (a1.y + b1.y) & (TABLE_N - 1);
        int p12 = (a1.z + b1.z) & (TABLE_N - 1);
        int p13 = (a1.w + b1.w) & (TABLE_N - 1);
        int m10 = (c1.x + d1.x) & (TABLE_N - 1);
        int m11 = (c1.y + d1.y) & (TABLE_N - 1);
        int m12 = (c1.z + d1.z) & (TABLE_N - 1);
        int m13 = (c1.w + d1.w) & (TABLE_N - 1);

        float2 A0 = phase_tab[p00], A1 = phase_tab[p01], A2 = phase_tab[p02], A3 = phase_tab[p03];
        float2 B0 = mag_tab[m00],   B1 = mag_tab[m01],   B2 = mag_tab[m02],   B3 = mag_tab[m03];
        float2 C0 = phase_tab[p10], C1 = phase_tab[p11], C2 = phase_tab[p12], C3 = phase_tab[p13];
        float2 E0 = mag_tab[m10],   E1 = mag_tab[m11],   E2 = mag_tab[m12],   E3 = mag_tab[m13];

        float s00 = A0.x * B0.x, s01 = A1.x * B1.x, s02 = A2.x * B2.x, s03 = A3.x * B3.x;
        float s10 = C0.x * E0.x, s11 = C1.x * E1.x, s12 = C2.x * E2.x, s13 = C3.x * E3.x;
        acc += ((s00 + s01) + (s02 + s03)) + ((s10 + s11) + (s12 + s13));

        // ---- stores grouped per stream: back-to-back 512B bursts = 1KB ----
        __stcs((float4*)out_phase + v0, make_float4((float)p00, (float)p01, (float)p02, (float)p03));
        __stcs((float4*)out_phase + v1, make_float4((float)p10, (float)p11, (float)p12, (float)p13));
        __stcs((float4*)out_mag + v0, make_float4((float)m00, (float)m01, (float)m02, (float)m03));
        __stcs((float4*)out_mag + v1, make_float4((float)m10, (float)m11, (float)m12, (float)m13));
        __stcs((float4*)out_sig + v0, make_float4(s00, s01, s02, s03));
        __stcs((float4*)out_sig + v1, make_float4(s10, s11, s12, s13));

        float gp00 = A0.y * B0.x, gp01 = A1.y * B1.x, gp02 = A2.y * B2.x, gp03 = A3.y * B3.x;
        float gm00 = A0.x * B0.y, gm01 = A1.x * B1.y, gm02 = A2.x * B2.y, gm03 = A3.x * B3.y;
        float gp10 = C0.y * E0.x, gp11 = C1.y * E1.x, gp12 = C2.y * E2.x, gp13 = C3.y * E3.x;
        float gm10 = C0.x * E0.y, gm11 = C1.x * E1.y, gm12 = C2.x * E2.y, gm13 = C3.x * E3.y;

        float q0 = __shfl_down_sync(0xFFFFFFFFu, gp00, 1);
        float q1 = __shfl_down_sync(0xFFFFFFFFu, gp01, 1);
        float q2 = __shfl_down_sync(0xFFFFFFFFu, gp02, 1);
        float r0 = __shfl_down_sync(0xFFFFFFFFu, gm00, 1);
        float r1 = __shfl_down_sync(0xFFFFFFFFu, gm01, 1);
        float r2 = __shfl_down_sync(0xFFFFFFFFu, gm02, 1);
        float u0 = __shfl_down_sync(0xFFFFFFFFu, gp10, 1);
        float u1 = __shfl_down_sync(0xFFFFFFFFu, gp11, 1);
        float u2 = __shfl_down_sync(0xFFFFFFFFu, gp12, 1);
        float w0 = __shfl_down_sync(0xFFFFFFFFu, gm10, 1);
        float w1 = __shfl_down_sync(0xFFFFFFFFu, gm11, 1);
        float w2 = __shfl_down_sync(0xFFFFFFFFu, gm12, 1);

        if (lane < 31) {
            __stcs((float4*)gp_base + v0 + 1, make_float4(gp03, q0, q1, q2));
            __stcs((float4*)gp_base + v1 + 1, make_float4(gp13, u0, u1, u2));
            __stcs((float4*)gm_base + v0 + 1, make_float4(gm03, r0, r1, r2));
            __stcs((float4*)gm_base + v1 + 1, make_float4(gm13, w0, w1, w2));
        } else {
            gp_base[4 * v0 + 4] = gp03;
            gm_base[4 * v0 + 4] = gm03;
            gp_base[4 * v1 + 4] = gp13;
            gm_base[4 * v1 + 4] = gm13;
        }
        if (lane == 0) {
            gp_base[4 * v0 + 1] = gp00;
            *(float2*)&gp_base[4 * v0 + 2] = make_float2(gp01, gp02);
            gm_base[4 * v0 + 1] = gm00;
            *(float2*)&gm_base[4 * v0 + 2] = make_float2(gm01, gm02);
            gp_base[4 * v1 + 1] = gp10;
            *(float2*)&gp_base[4 * v1 + 2] = make_float2(gp11, gp12);
            gm_base[4 * v1 + 1] = gm10;
            *(float2*)&gm_base[4 * v1 + 2] = make_float2(gm11, gm12);
        }
    }

#if __CUDA_ARCH__ >= 900
    cudaTriggerProgrammaticLaunchCompletion();
#endif

    // Deterministic block reduction
    #pragma unroll
    for (int off = 16; off > 0; off >>= 1)
        acc += __shfl_down_sync(0xFFFFFFFFu, acc, off);
    if (lane == 0) red[tid >> 5] = acc;
    __syncthreads();
    if (tid == 0) {
        float s = 0.0f;
        #pragma unroll
        for (int w = 0; w < NTHREADS / 32; w++) s += red[w];
        g_partials[blockIdx.x] = s;
        __threadfence();                       // release partial
        atomicAdd(&g_counter, 1u);             // signal completion
    }
}

__global__ __launch_bounds__(1024) void phasecell_reduce(float* __restrict__ out)
{
    __shared__ float red[32];
    const int tid = threadIdx.x;

    // Data-level handshake: wait until all primary blocks released partials.
    if (tid == 0) {
        while (atomicAdd(&g_counter, 0u) < (unsigned)NBLOCKS) {
#if __CUDA_ARCH__ >= 700
            __nanosleep(64);
#endif
        }
        __threadfence();                       // acquire
    }
    __syncthreads();

    // 1184 partials = 296 float4 vectors: single load round (L2).
    float a = 0.0f;
    if (tid < NBLOCKS / 4) {
        const float* p = &g_partials[tid * 4];
        float x = __ldcg(&p[0]);
        float y = __ldcg(&p[1]);
        float z = __ldcg(&p[2]);
        float w = __ldcg(&p[3]);
        a = (x + y) + (z + w);
    }
    #pragma unroll
    for (int off = 16; off > 0; off >>= 1)
        a += __shfl_down_sync(0xFFFFFFFFu, a, off);
    if ((tid & 31) == 0) red[tid >> 5] = a;
    __syncthreads();
    if (tid == 0) {
        float s = 0.0f;
        #pragma unroll
        for (int w = 0; w < 32; w++) s += red[w];
        out[(size_t)3 * D_TOTAL] = s;  // strength scalar
        g_counter = 0;                 // reset for next graph replay
    }
}

extern "C" void kernel_launch(void* const* d_in, const int* in_sizes, int n_in,
                              void* d_out, int out_size)
{
    const int*   ctx_phase  = (const int*)d_in[0];
    const int*   ctx_mag    = (const int*)d_in[1];
    const int*   self_phase = (const int*)d_in[2];
    const int*   self_mag   = (const int*)d_in[3];
    const float* cos_t      = (const float*)d_in[4];
    const float* exp_t      = (const float*)d_in[5];
    const float* cos_g      = (const float*)d_in[6];
    const float* exp_g      = (const float*)d_in[7];
    float* out = (float*)d_out;

    phasecell_main<<<NBLOCKS, NTHREADS>>>(ctx_phase, ctx_mag, self_phase, self_mag,
                                          cos_t, exp_t, cos_g, exp_g, out);

    cudaLaunchConfig_t cfg = {};
    cfg.gridDim  = dim3(1, 1, 1);
    cfg.blockDim = dim3(1024, 1, 1);
    cfg.dynamicSmemBytes = 0;
    cfg.stream = 0;

    cudaLaunchAttribute attrs[1];
    attrs[0].id = cudaLaunchAttributeProgrammaticStreamSerialization;
    attrs[0].val.programmaticStreamSerializationAllowed = 1;
    cfg.attrs = attrs;
    cfg.numAttrs = 1;

    cudaError_t e = cudaLaunchKernelEx(&cfg, phasecell_reduce, out);
    if (e != cudaSuccess) {
        phasecell_reduce<<<1, 1024>>>(out);
    }
}

// round 15
// speedup vs baseline: 1.0316x; 1.0028x over previous
#include <cuda_runtime.h>
#include <cuda_bf16.h>

#define D_TOTAL   8388608
#define TABLE_N   1024
#define NBLOCKS   1184   /* 8 x 148 effective SMs — max occupancy, empirically best */
#define NTHREADS  256

__device__ float g_partials[NBLOCKS];
__device__ unsigned int g_counter = 0;

__global__ __launch_bounds__(NTHREADS) void phasecell_main(
    const int* __restrict__ ctx_phase,
    const int* __restrict__ ctx_mag,
    const int* __restrict__ self_phase,
    const int* __restrict__ self_mag,
    const float* __restrict__ cos_table,
    const float* __restrict__ exp_table,
    const float* __restrict__ cos_grad_table,
    const float* __restrict__ exp_grad_table,
    float* __restrict__ out)
{
    __shared__ float2 phase_tab[TABLE_N];  // (cos, dcos)
    __shared__ float2 mag_tab[TABLE_N];    // (exp, dexp)
    __shared__ float red[NTHREADS / 32];

    const int tid  = threadIdx.x;
    const int lane = tid & 31;
    for (int i = tid; i < TABLE_N; i += NTHREADS) {
        phase_tab[i] = make_float2(cos_table[i], cos_grad_table[i]);
        mag_tab[i]   = make_float2(exp_table[i], exp_grad_table[i]);
    }
    __syncthreads();

    const int4* cp4 = (const int4*)ctx_phase;
    const int4* sp4 = (const int4*)self_phase;
    const int4* cm4 = (const int4*)ctx_mag;
    const int4* sm4 = (const int4*)self_mag;

    float* __restrict__ out_phase = out;
    float* __restrict__ out_mag   = out + (size_t)D_TOTAL;
    float* __restrict__ out_sig   = out + (size_t)2 * D_TOTAL;
    // grad streams start at odd float offset (3D+1)/(4D+1); aligned-shifted
    // store scheme below. These bases are 16B-aligned.
    float* __restrict__ gp_base = out + (size_t)3 * D_TOTAL;
    float* __restrict__ gm_base = out + (size_t)4 * D_TOTAL;

    // Warp-chunked round-robin: chunk = 64 consecutive float4 vectors (1KB
    // per stream per warp). nvec = 2^21 = 64 * 32768 exactly.
    const int nchunks = (D_TOTAL / 4) / 64;                      // 32768
    const int nwarps  = gridDim.x * (NTHREADS / 32);             // 9472
    const int wglobal = (blockIdx.x * NTHREADS + tid) >> 5;

    float acc = 0.0f;

    for (int ch = wglobal; ch < nchunks; ch += nwarps) {
        const int v0 = ch * 64 + lane;
        const int v1 = v0 + 32;

        // ---- all loads grouped: 8x LDG.128, two 512B bursts per stream ----
        int4 a0 = __ldcs(&cp4[v0]); int4 a1 = __ldcs(&cp4[v1]);
        int4 b0 = __ldcs(&sp4[v0]); int4 b1 = __ldcs(&sp4[v1]);
        int4 c0 = __ldcs(&cm4[v0]); int4 c1 = __ldcs(&cm4[v1]);
        int4 d0 = __ldcs(&sm4[v0]); int4 d1 = __ldcs(&sm4[v1]);

        int p00 = (a0.x + b0.x) & (TABLE_N - 1);
        int p01 = (a0.y + b0.y) & (TABLE_N - 1);
        int p02 = (a0.z + b0.z) & (TABLE_N - 1);
        int p03 = (a0.w + b0.w) & (TABLE_N - 1);
        int m00 = (c0.x + d0.x) & (TABLE_N - 1);
        int m01 = (c0.y + d0.y) & (TABLE_N - 1);
        int m02 = (c0.z + d0.z) & (TABLE_N - 1);
        int m03 = (c0.w + d0.w) & (TABLE_N - 1);
        int p10 = (a1.x + b1.x) & (TABLE_N - 1);
        int p11 = (a1.y + b1.y) & (TABLE_N - 1);
        int p12 = (a1.z + b1.z) & (TABLE_N - 1);
        int p13 = (a1.w + b1.w) & (TABLE_N - 1);
        int m10 = (c1.x + d1.x) & (TABLE_N - 1);
        int m11 = (c1.y + d1.y) & (TABLE_N - 1);
        int m12 = (c1.z + d1.z) & (TABLE_N - 1);
        int m13 = (c1.w + d1.w) & (TABLE_N - 1);

        float2 A0 = phase_tab[p00], A1 = phase_tab[p01], A2 = phase_tab[p02], A3 = phase_tab[p03];
        float2 B0 = mag_tab[m00],   B1 = mag_tab[m01],   B2 = mag_tab[m02],   B3 = mag_tab[m03];
        float2 C0 = phase_tab[p10], C1 = phase_tab[p11], C2 = phase_tab[p12], C3 = phase_tab[p13];
        float2 E0 = mag_tab[m10],   E1 = mag_tab[m11],   E2 = mag_tab[m12],   E3 = mag_tab[m13];

        float s00 = A0.x * B0.x, s01 = A1.x * B1.x, s02 = A2.x * B2.x, s03 = A3.x * B3.x;
        float s10 = C0.x * E0.x, s11 = C1.x * E1.x, s12 = C2.x * E2.x, s13 = C3.x * E3.x;
        acc += ((s00 + s01) + (s02 + s03)) + ((s10 + s11) + (s12 + s13));

        // ---- stores grouped per stream: back-to-back 512B bursts = 1KB ----
        __stcs((float4*)out_phase + v0, make_float4((float)p00, (float)p01, (float)p02, (float)p03));
        __stcs((float4*)out_phase + v1, make_float4((float)p10, (float)p11, (float)p12, (float)p13));
        __stcs((float4*)out_mag + v0, make_float4((float)m00, (float)m01, (float)m02, (float)m03));
        __stcs((float4*)out_mag + v1, make_float4((float)m10, (float)m11, (float)m12, (float)m13));
        __stcs((float4*)out_sig + v0, make_float4(s00, s01, s02, s03));
        __stcs((float4*)out_sig + v1, make_float4(s10, s11, s12, s13));

        float gp00 = A0.y * B0.x, gp01 = A1.y * B1.x, gp02 = A2.y * B2.x, gp03 = A3.y * B3.x;
        float gm00 = A0.x * B0.y, gm01 = A1.x * B1.y, gm02 = A2.x * B2.y, gm03 = A3.x * B3.y;
        float gp10 = C0.y * E0.x, gp11 = C1.y * E1.x, gp12 = C2.y * E2.x, gp13 = C3.y * E3.x;
        float gm10 = C0.x * E0.y, gm11 = C1.x * E1.y, gm12 = C2.x * E2.y, gm13 = C3.x * E3.y;

        float q0 = __shfl_down_sync(0xFFFFFFFFu, gp00, 1);
        float q1 = __shfl_down_sync(0xFFFFFFFFu, gp01, 1);
        float q2 = __shfl_down_sync(0xFFFFFFFFu, gp02, 1);
        float r0 = __shfl_down_sync(0xFFFFFFFFu, gm00, 1);
        float r1 = __shfl_down_sync(0xFFFFFFFFu, gm01, 1);
        float r2 = __shfl_down_sync(0xFFFFFFFFu, gm02, 1);
        float u0 = __shfl_down_sync(0xFFFFFFFFu, gp10, 1);
        float u1 = __shfl_down_sync(0xFFFFFFFFu, gp11, 1);
        float u2 = __shfl_down_sync(0xFFFFFFFFu, gp12, 1);
        float w0 = __shfl_down_sync(0xFFFFFFFFu, gm10, 1);
        float w1 = __shfl_down_sync(0xFFFFFFFFu, gm11, 1);
        float w2 = __shfl_down_sync(0xFFFFFFFFu, gm12, 1);

        if (lane < 31) {
            __stcs((float4*)gp_base + v0 + 1, make_float4(gp03, q0, q1, q2));
            __stcs((float4*)gp_base + v1 + 1, make_float4(gp13, u0, u1, u2));
            __stcs((float4*)gm_base + v0 + 1, make_float4(gm03, r0, r1, r2));
            __stcs((float4*)gm_base + v1 + 1, make_float4(gm13, w0, w1, w2));
        } else {
            gp_base[4 * v0 + 4] = gp03;
            gm_base[4 * v0 + 4] = gm03;
            gp_base[4 * v1 + 4] = gp13;
            gm_base[4 * v1 + 4] = gm13;
        }
        if (lane == 0) {
            gp_base[4 * v0 + 1] = gp00;
            *(float2*)&gp_base[4 * v0 + 2] = make_float2(gp01, gp02);
            gm_base[4 * v0 + 1] = gm00;
            *(float2*)&gm_base[4 * v0 + 2] = make_float2(gm01, gm02);
            gp_base[4 * v1 + 1] = gp10;
            *(float2*)&gp_base[4 * v1 + 2] = make_float2(gp11, gp12);
            gm_base[4 * v1 + 1] = gm10;
            *(float2*)&gm_base[4 * v1 + 2] = make_float2(gm11, gm12);
        }
    }

#if __CUDA_ARCH__ >= 900
    cudaTriggerProgrammaticLaunchCompletion();
#endif

    // Deterministic block reduction
    #pragma unroll
    for (int off = 16; off > 0; off >>= 1)
        acc += __shfl_down_sync(0xFFFFFFFFu, acc, off);
    if (lane == 0) red[tid >> 5] = acc;
    __syncthreads();
    if (tid == 0) {
        float s = 0.0f;
        #pragma unroll
        for (int w = 0; w < NTHREADS / 32; w++) s += red[w];
        g_partials[blockIdx.x] = s;
        __threadfence();                       // release partial
        atomicAdd(&g_counter, 1u);             // signal completion
    }
}

__global__ __launch_bounds__(1024) void phasecell_reduce(float* __restrict__ out)
{
    __shared__ float red[32];
    const int tid = threadIdx.x;

    // Data-level handshake: wait until all primary blocks released partials.
    if (tid == 0) {
        while (atomicAdd(&g_counter, 0u) < (unsigned)NBLOCKS) {
#if __CUDA_ARCH__ >= 700
            __nanosleep(64);
#endif
        }
        __threadfence();                       // acquire
    }
    __syncthreads();

    // 1184 partials = 296 float4 vectors: single load round (L2).
    float a = 0.0f;
    if (tid < NBLOCKS / 4) {
        const float* p = &g_partials[tid * 4];
        float x = __ldcg(&p[0]);
        float y = __ldcg(&p[1]);
        float z = __ldcg(&p[2]);
        float w = __ldcg(&p[3]);
        a = (x + y) + (z + w);
    }
    #pragma unroll
    for (int off = 16; off > 0; off >>= 1)
        a += __shfl_down_sync(0xFFFFFFFFu, a, off);
    if ((tid & 31) == 0) red[tid >> 5] = a;
    __syncthreads();
    if (tid == 0) {
        float s = 0.0f;
        #pragma unroll
        for (int w = 0; w < 32; w++) s += red[w];
        out[(size_t)3 * D_TOTAL] = s;  // strength scalar
        g_counter = 0;                 // reset for next graph replay
    }
}

extern "C" void kernel_launch(void* const* d_in, const int* in_sizes, int n_in,
                              void* d_out, int out_size)
{
    const int*   ctx_phase  = (const int*)d_in[0];
    const int*   ctx_mag    = (const int*)d_in[1];
    const int*   self_phase = (const int*)d_in[2];
    const int*   self_mag   = (const int*)d_in[3];
    const float* cos_t      = (const float*)d_in[4];
    const float* exp_t      = (const float*)d_in[5];
    const float* cos_g      = (const float*)d_in[6];
    const float* exp_g      = (const float*)d_in[7];
    float* out = (float*)d_out;

    phasecell_main<<<NBLOCKS, NTHREADS>>>(ctx_phase, ctx_mag, self_phase, self_mag,
                                          cos_t, exp_t, cos_g, exp_g, out);

    cudaLaunchConfig_t cfg = {};
    cfg.gridDim  = dim3(1, 1, 1);
    cfg.blockDim = dim3(1024, 1, 1);
    cfg.dynamicSmemBytes = 0;
    cfg.stream = 0;

    cudaLaunchAttribute attrs[1];
    attrs[0].id = cudaLaunchAttributeProgrammaticStreamSerialization;
    attrs[0].val.programmaticStreamSerializationAllowed = 1;
    cfg.attrs = attrs;
    cfg.numAttrs = 1;

    cudaError_t e = cudaLaunchKernelEx(&cfg, phasecell_reduce, out);
    if (e != cudaSuccess) {
        phasecell_reduce<<<1, 1024>>>(out);
    }
}

// round 16
// speedup vs baseline: 1.0499x; 1.0178x over previous
#include <cuda_runtime.h>
#include <cuda_bf16.h>

#define D_TOTAL   8388608
#define TABLE_N   1024
#define NBLOCKS   1184   /* 8 x 148 effective SMs — max occupancy, empirically best */
#define NTHREADS  256

__device__ float g_partials[NBLOCKS];
__device__ unsigned int g_counter = 0;

__global__ __launch_bounds__(NTHREADS) void phasecell_main(
    const int* __restrict__ ctx_phase,
    const int* __restrict__ ctx_mag,
    const int* __restrict__ self_phase,
    const int* __restrict__ self_mag,
    const float* __restrict__ cos_table,
    const float* __restrict__ exp_table,
    const float* __restrict__ cos_grad_table,
    const float* __restrict__ exp_grad_table,
    float* __restrict__ out)
{
    __shared__ float2 phase_tab[TABLE_N];  // (cos, dcos)
    __shared__ float2 mag_tab[TABLE_N];    // (exp, dexp)
    __shared__ float red[NTHREADS / 32];

    const int tid  = threadIdx.x;
    const int lane = tid & 31;
    for (int i = tid; i < TABLE_N; i += NTHREADS) {
        phase_tab[i] = make_float2(cos_table[i], cos_grad_table[i]);
        mag_tab[i]   = make_float2(exp_table[i], exp_grad_table[i]);
    }
    __syncthreads();

    const int4* cp4 = (const int4*)ctx_phase;
    const int4* sp4 = (const int4*)self_phase;
    const int4* cm4 = (const int4*)ctx_mag;
    const int4* sm4 = (const int4*)self_mag;

    float* __restrict__ out_phase = out;
    float* __restrict__ out_mag   = out + (size_t)D_TOTAL;
    float* __restrict__ out_sig   = out + (size_t)2 * D_TOTAL;
    // grad streams start at odd float offset (3D+1)/(4D+1); aligned-shifted
    // store scheme below. These bases are 16B-aligned.
    float* __restrict__ gp_base = out + (size_t)3 * D_TOTAL;
    float* __restrict__ gm_base = out + (size_t)4 * D_TOTAL;

    // Warp-chunked round-robin: chunk = 64 consecutive float4 vectors (1KB
    // per stream per warp). nvec = 2^21 = 64 * 32768 exactly.
    const int nchunks = (D_TOTAL / 4) / 64;                      // 32768
    const int nwarps  = gridDim.x * (NTHREADS / 32);             // 9472
    const int wglobal = (blockIdx.x * NTHREADS + tid) >> 5;

    float acc = 0.0f;

    for (int ch = wglobal; ch < nchunks; ch += nwarps) {
        const int v0 = ch * 64 + lane;
        const int v1 = v0 + 32;

        // ---- all loads grouped: 8x LDG.128, two 512B bursts per stream ----
        int4 a0 = __ldcs(&cp4[v0]); int4 a1 = __ldcs(&cp4[v1]);
        int4 b0 = __ldcs(&sp4[v0]); int4 b1 = __ldcs(&sp4[v1]);
        int4 c0 = __ldcs(&cm4[v0]); int4 c1 = __ldcs(&cm4[v1]);
        int4 d0 = __ldcs(&sm4[v0]); int4 d1 = __ldcs(&sm4[v1]);

        int p00 = (a0.x + b0.x) & (TABLE_N - 1);
        int p01 = (a0.y + b0.y) & (TABLE_N - 1);
        int p02 = (a0.z + b0.z) & (TABLE_N - 1);
        int p03 = (a0.w + b0.w) & (TABLE_N - 1);
        int m00 = (c0.x + d0.x) & (TABLE_N - 1);
        int m01 = (c0.y + d0.y) & (TABLE_N - 1);
        int m02 = (c0.z + d0.z) & (TABLE_N - 1);
        int m03 = (c0.w + d0.w) & (TABLE_N - 1);
        int p10 = (a1.x + b1.x) & (TABLE_N - 1);
        int p11 = (a1.y + b1.y) & (TABLE_N - 1);
        int p12 = (a1.z + b1.z) & (TABLE_N - 1);
        int p13 = (a1.w + b1.w) & (TABLE_N - 1);
        int m10 = (c1.x + d1.x) & (TABLE_N - 1);
        int m11 = (c1.y + d1.y) & (TABLE_N - 1);
        int m12 = (c1.z + d1.z) & (TABLE_N - 1);
        int m13 = (c1.w + d1.w) & (TABLE_N - 1);

        float2 A0 = phase_tab[p00], A1 = phase_tab[p01], A2 = phase_tab[p02], A3 = phase_tab[p03];
        float2 B0 = mag_tab[m00],   B1 = mag_tab[m01],   B2 = mag_tab[m02],   B3 = mag_tab[m03];
        float2 C0 = phase_tab[p10], C1 = phase_tab[p11], C2 = phase_tab[p12], C3 = phase_tab[p13];
        float2 E0 = mag_tab[m10],   E1 = mag_tab[m11],   E2 = mag_tab[m12],   E3 = mag_tab[m13];

        float s00 = A0.x * B0.x, s01 = A1.x * B1.x, s02 = A2.x * B2.x, s03 = A3.x * B3.x;
        float s10 = C0.x * E0.x, s11 = C1.x * E1.x, s12 = C2.x * E2.x, s13 = C3.x * E3.x;
        acc += ((s00 + s01) + (s02 + s03)) + ((s10 + s11) + (s12 + s13));

        // ---- stores grouped per stream: back-to-back 512B bursts = 1KB ----
        __stcs((float4*)out_phase + v0, make_float4((float)p00, (float)p01, (float)p02, (float)p03));
        __stcs((float4*)out_phase + v1, make_float4((float)p10, (float)p11, (float)p12, (float)p13));
        __stcs((float4*)out_mag + v0, make_float4((float)m00, (float)m01, (float)m02, (float)m03));
        __stcs((float4*)out_mag + v1, make_float4((float)m10, (float)m11, (float)m12, (float)m13));
        __stcs((float4*)out_sig + v0, make_float4(s00, s01, s02, s03));
        __stcs((float4*)out_sig + v1, make_float4(s10, s11, s12, s13));

        float gp00 = A0.y * B0.x, gp01 = A1.y * B1.x, gp02 = A2.y * B2.x, gp03 = A3.y * B3.x;
        float gm00 = A0.x * B0.y, gm01 = A1.x * B1.y, gm02 = A2.x * B2.y, gm03 = A3.x * B3.y;
        float gp10 = C0.y * E0.x, gp11 = C1.y * E1.x, gp12 = C2.y * E2.x, gp13 = C3.y * E3.x;
        float gm10 = C0.x * E0.y, gm11 = C1.x * E1.y, gm12 = C2.x * E2.y, gm13 = C3.x * E3.y;

        float q0 = __shfl_down_sync(0xFFFFFFFFu, gp00, 1);
        float q1 = __shfl_down_sync(0xFFFFFFFFu, gp01, 1);
        float q2 = __shfl_down_sync(0xFFFFFFFFu, gp02, 1);
        float r0 = __shfl_down_sync(0xFFFFFFFFu, gm00, 1);
        float r1 = __shfl_down_sync(0xFFFFFFFFu, gm01, 1);
        float r2 = __shfl_down_sync(0xFFFFFFFFu, gm02, 1);
        float u0 = __shfl_down_sync(0xFFFFFFFFu, gp10, 1);
        float u1 = __shfl_down_sync(0xFFFFFFFFu, gp11, 1);
        float u2 = __shfl_down_sync(0xFFFFFFFFu, gp12, 1);
        float w0 = __shfl_down_sync(0xFFFFFFFFu, gm10, 1);
        float w1 = __shfl_down_sync(0xFFFFFFFFu, gm11, 1);
        float w2 = __shfl_down_sync(0xFFFFFFFFu, gm12, 1);

        if (lane < 31) {
            __stcs((float4*)gp_base + v0 + 1, make_float4(gp03, q0, q1, q2));
            __stcs((float4*)gp_base + v1 + 1, make_float4(gp13, u0, u1, u2));
            __stcs((float4*)gm_base + v0 + 1, make_float4(gm03, r0, r1, r2));
            __stcs((float4*)gm_base + v1 + 1, make_float4(gm13, w0, w1, w2));
        } else {
            gp_base[4 * v0 + 4] = gp03;
            gm_base[4 * v0 + 4] = gm03;
            gp_base[4 * v1 + 4] = gp13;
            gm_base[4 * v1 + 4] = gm13;
        }
        if (lane == 0) {
            gp_base[4 * v0 + 1] = gp00;
            *(float2*)&gp_base[4 * v0 + 2] = make_float2(gp01, gp02);
            gm_base[4 * v0 + 1] = gm00;
            *(float2*)&gm_base[4 * v0 + 2] = make_float2(gm01, gm02);
            gp_base[4 * v1 + 1] = gp10;
            *(float2*)&gp_base[4 * v1 + 2] = make_float2(gp11, gp12);
            gm_base[4 * v1 + 1] = gm10;
            *(float2*)&gm_base[4 * v1 + 2] = make_float2(gm11, gm12);
        }
    }

#if __CUDA_ARCH__ >= 900
    cudaTriggerProgrammaticLaunchCompletion();
#endif

    // Deterministic block reduction
    #pragma unroll
    for (int off = 16; off > 0; off >>= 1)
        acc += __shfl_down_sync(0xFFFFFFFFu, acc, off);
    if (lane == 0) red[tid >> 5] = acc;
    __syncthreads();
    if (tid == 0) {
        float s = 0.0f;
        #pragma unroll
        for (int w = 0; w < NTHREADS / 32; w++) s += red[w];
        g_partials[blockIdx.x] = s;
        __threadfence();                       // release partial
        atomicAdd(&g_counter, 1u);             // signal completion
    }
}

__global__ __launch_bounds__(1024) void phasecell_reduce(float* __restrict__ out)
{
    __shared__ float red[32];
    const int tid = threadIdx.x;

    // Data-level handshake: wait until all primary blocks released partials.
    if (tid == 0) {
        while (atomicAdd(&g_counter, 0u) < (unsigned)NBLOCKS) {
#if __CUDA_ARCH__ >= 700
            __nanosleep(64);
#endif
        }
        __threadfence();                       // acquire
    }
    __syncthreads();

    // 1184 partials = 296 float4 vectors: single load round (L2).
    float a = 0.0f;
    if (tid < NBLOCKS / 4) {
        const float* p = &g_partials[tid * 4];
        float x = __ldcg(&p[0]);
        float y = __ldcg(&p[1]);
        float z = __ldcg(&p[2]);
        float w = __ldcg(&p[3]);
        a = (x + y) + (z + w);
    }
    #pragma unroll
    for (int off = 16; off > 0; off >>= 1)
        a += __shfl_down_sync(0xFFFFFFFFu, a, off);
    if ((tid & 31) == 0) red[tid >> 5] = a;
    __syncthreads();
    if (tid == 0) {
        float s = 0.0f;
        #pragma unroll
        for (int w = 0; w < 32; w++) s += red[w];
        out[(size_t)3 * D_TOTAL] = s;  // strength scalar
        g_counter = 0;                 // reset for next graph replay
    }
}

extern "C" void kernel_launch(void* const* d_in, const int* in_sizes, int n_in,
                              void* d_out, int out_size)
{
    const int*   ctx_phase  = (const int*)d_in[0];
    const int*   ctx_mag    = (const int*)d_in[1];
    const int*   self_phase = (const int*)d_in[2];
    const int*   self_mag   = (const int*)d_in[3];
    const float* cos_t      = (const float*)d_in[4];
    const float* exp_t      = (const float*)d_in[5];
    const float* cos_g      = (const float*)d_in[6];
    const float* exp_g      = (const float*)d_in[7];
    float* out = (float*)d_out;

    phasecell_main<<<NBLOCKS, NTHREADS>>>(ctx_phase, ctx_mag, self_phase, self_mag,
                                          cos_t, exp_t, cos_g, exp_g, out);

    cudaLaunchConfig_t cfg = {};
    cfg.gridDim  = dim3(1, 1, 1);
    cfg.blockDim = dim3(1024, 1, 1);
    cfg.dynamicSmemBytes = 0;
    cfg.stream = 0;

    cudaLaunchAttribute attrs[1];
    attrs[0].id = cudaLaunchAttributeProgrammaticStreamSerialization;
    attrs[0].val.programmaticStreamSerializationAllowed = 1;
    cfg.attrs = attrs;
    cfg.numAttrs = 1;

    cudaError_t e = cudaLaunchKernelEx(&cfg, phasecell_reduce, out);
    if (e != cudaSuccess) {
        phasecell_reduce<<<1, 1024>>>(out);
    }
}